// round 4
// baseline (speedup 1.0000x reference)
#include <cuda_runtime.h>
#include <cuda_bf16.h>
#include <cstdint>

// ============================================================================
// out[4096,4096] = x @ W^T + b  (fp32).
// fp32 -> bf16 hi/lo split; 3-product warp-MMA (mma.sync m16n8k16 bf16) GEMM.
// CTA tile 128x256x32, 8 warps @ 64x64, 4-stage cp.async pipeline.
// ============================================================================

#define DIM 4096
#define BM 128
#define BN 256
#define BK 32
#define NKT (DIM / BK)          // 128 k-tiles
#define THREADS 256
#define STAGES 4

// per-stage smem: Ah 8K | Al 8K | Bh 16K | Bl 16K = 48KB (64B rows, XOR swizzle)
#define STAGE_BYTES 49152
#define OFF_AH 0
#define OFF_AL 8192
#define OFF_BH 16384
#define OFF_BL 32768
#define SM_BIAS 0               // 256 floats
#define SM_TILES 1024
#define SMEM_TOTAL (SM_TILES + STAGES * STAGE_BYTES)   // 197632

// ---------------------------------------------------------------------------
// Scratch: bf16 hi/lo splits of x and W
// ---------------------------------------------------------------------------
__device__ __align__(256) __nv_bfloat16 g_xh[(size_t)DIM * DIM];
__device__ __align__(256) __nv_bfloat16 g_xl[(size_t)DIM * DIM];
__device__ __align__(256) __nv_bfloat16 g_wh[(size_t)DIM * DIM];
__device__ __align__(256) __nv_bfloat16 g_wl[(size_t)DIM * DIM];

// ---------------------------------------------------------------------------
// Helpers
// ---------------------------------------------------------------------------
static __device__ __forceinline__ uint32_t smem_u32(const void* p) {
    uint32_t a;
    asm("{ .reg .u64 t; cvta.to.shared.u64 t, %1; cvt.u32.u64 %0, t; }"
        : "=r"(a) : "l"(p));
    return a;
}

static __device__ __forceinline__ void cp16(uint32_t s, const void* g) {
    asm volatile("cp.async.cg.shared.global [%0], [%1], 16;" :: "r"(s), "l"(g));
}

static __device__ __forceinline__ void ldsm4(uint32_t* r, uint32_t a) {
    asm volatile("ldmatrix.sync.aligned.m8n8.x4.shared.b16 {%0,%1,%2,%3}, [%4];"
                 : "=r"(r[0]), "=r"(r[1]), "=r"(r[2]), "=r"(r[3]) : "r"(a));
}

static __device__ __forceinline__ void mma16816(float* c, const uint32_t* a,
                                                const uint32_t* b) {
    asm volatile(
        "mma.sync.aligned.m16n8k16.row.col.f32.bf16.bf16.f32 "
        "{%0,%1,%2,%3}, {%4,%5,%6,%7}, {%8,%9}, {%0,%1,%2,%3};"
        : "+f"(c[0]), "+f"(c[1]), "+f"(c[2]), "+f"(c[3])
        : "r"(a[0]), "r"(a[1]), "r"(a[2]), "r"(a[3]), "r"(b[0]), "r"(b[1]));
}

// ---------------------------------------------------------------------------
// Split kernel: fp32 -> bf16 hi + bf16 lo residual
// ---------------------------------------------------------------------------
__global__ __launch_bounds__(256) void split_kernel(const float* __restrict__ src,
                                                    int which) {
    __nv_bfloat16* hi = which ? g_wh : g_xh;
    __nv_bfloat16* lo = which ? g_wl : g_xl;
    size_t i = ((size_t)blockIdx.x * blockDim.x + threadIdx.x) * 4;
    float4 v = *reinterpret_cast<const float4*>(src + i);
    float vv[4] = {v.x, v.y, v.z, v.w};
    uint32_t h[4], l[4];
#pragma unroll
    for (int j = 0; j < 4; ++j) {
        __nv_bfloat16 hb = __float2bfloat16_rn(vv[j]);
        float r = vv[j] - __bfloat162float(hb);
        __nv_bfloat16 lb = __float2bfloat16_rn(r);
        h[j] = (uint32_t)__bfloat16_as_ushort(hb);
        l[j] = (uint32_t)__bfloat16_as_ushort(lb);
    }
    *reinterpret_cast<uint2*>(hi + i) = make_uint2(h[0] | (h[1] << 16), h[2] | (h[3] << 16));
    *reinterpret_cast<uint2*>(lo + i) = make_uint2(l[0] | (l[1] << 16), l[2] | (l[3] << 16));
}

// ---------------------------------------------------------------------------
// Stage loader: rows 64B wide; chunk c of row r stored at
//   r*64 + ((c ^ ((r>>1)&3))<<4)  -> conflict-free for cp.async AND ldmatrix.
// A: 128 rows (512 chunks x2), B: 256 rows (1024 chunks x2) -> 12 cp16/thread.
// ---------------------------------------------------------------------------
static __device__ __forceinline__ void load_stage(uint32_t sb, int stage, int kt,
                                                  int tm, int tn, int tid) {
    uint32_t st = sb + SM_TILES + stage * STAGE_BYTES;
    const uint32_t k0 = (uint32_t)kt * BK;
    // A: 512 chunks over 256 threads
#pragma unroll
    for (int i = 0; i < 2; ++i) {
        int c = i * 256 + tid;
        int r = c >> 2, cc = c & 3;
        uint32_t so = (uint32_t)r * 64 + (uint32_t)((cc ^ ((r >> 1) & 3)) << 4);
        size_t gA = (size_t)(tm * BM + r) * DIM + k0 + cc * 8;
        cp16(st + OFF_AH + so, g_xh + gA);
        cp16(st + OFF_AL + so, g_xl + gA);
    }
    // B: 1024 chunks over 256 threads
#pragma unroll
    for (int i = 0; i < 4; ++i) {
        int c = i * 256 + tid;
        int r = c >> 2, cc = c & 3;
        uint32_t so = (uint32_t)r * 64 + (uint32_t)((cc ^ ((r >> 1) & 3)) << 4);
        size_t gB = (size_t)(tn * BN + r) * DIM + k0 + cc * 8;
        cp16(st + OFF_BH + so, g_wh + gB);
        cp16(st + OFF_BL + so, g_wl + gB);
    }
}

// ---------------------------------------------------------------------------
// GEMM: D(128x256) += Ah*Bh + Ah*Bl + Al*Bh over K, then +bias.
// 8 warps: wm = wid&1 (2 x 64 rows), wn = wid>>1 (4 x 64 cols).
// ---------------------------------------------------------------------------
__global__ __launch_bounds__(THREADS, 1) void gemm_kernel(const float* __restrict__ bias,
                                                          float* __restrict__ out) {
    extern __shared__ __align__(1024) char smem[];
    uint32_t sb = smem_u32(smem);
    const int tid = threadIdx.x;
    const int lane = tid & 31, wid = tid >> 5;
    const int wm = wid & 1, wn = wid >> 1;

    // panel raster: panels of (8 tm x 16 tn) = 128 CTAs; wave ~fits in L2
    const int pid = blockIdx.x;
    const int panel = pid >> 7;            // 0..3
    const int ip = pid & 127;
    const int tm = panel * 8 + (ip & 7);   // 0..31
    const int tn = ip >> 3;                // 0..15

    reinterpret_cast<float*>(smem + SM_BIAS)[tid] = bias[tn * BN + tid];

    // per-lane ldmatrix address components (row*64 base + row-swizzle key)
    uint32_t aoff[4], asw[4];
#pragma unroll
    for (int mt = 0; mt < 4; ++mt) {
        int r = wm * 64 + mt * 16 + (lane & 15);
        aoff[mt] = (uint32_t)r * 64;
        asw[mt] = (uint32_t)((r >> 1) & 3);
    }
    uint32_t boff[4], bsw[4];
#pragma unroll
    for (int jj = 0; jj < 4; ++jj) {
        int r = wn * 64 + jj * 16 + ((lane >> 4) & 1) * 8 + (lane & 7);
        boff[jj] = (uint32_t)r * 64;
        bsw[jj] = (uint32_t)((r >> 1) & 3);
    }
    const uint32_t cAsel = (uint32_t)(lane >> 4);        // A k-chunk select
    const uint32_t cBsel = (uint32_t)((lane >> 3) & 1);  // B k-chunk select

    float acc[4][8][4];
#pragma unroll
    for (int mt = 0; mt < 4; ++mt)
#pragma unroll
        for (int nt = 0; nt < 8; ++nt)
#pragma unroll
            for (int k = 0; k < 4; ++k) acc[mt][nt][k] = 0.f;

    // prologue: 3 stages in flight
#pragma unroll
    for (int s = 0; s < STAGES - 1; ++s) {
        load_stage(sb, s, s, tm, tn, tid);
        asm volatile("cp.async.commit_group;");
    }

    for (int t = 0; t < NKT; ++t) {
        asm volatile("cp.async.wait_group 2;");
        __syncthreads();

        if (t + STAGES - 1 < NKT)
            load_stage(sb, (t + STAGES - 1) & (STAGES - 1), t + STAGES - 1, tm, tn, tid);
        asm volatile("cp.async.commit_group;");   // empty group ok -> uniform counting

        const uint32_t stg = sb + SM_TILES + (uint32_t)(t & (STAGES - 1)) * STAGE_BYTES;
#pragma unroll
        for (int s = 0; s < 2; ++s) {             // two k16 steps per BK=32
            uint32_t ah[4][4], al[4][4];
#pragma unroll
            for (int mt = 0; mt < 4; ++mt) {
                uint32_t ca = (uint32_t)(2 * s) + cAsel;
                uint32_t ad = stg + aoff[mt] + ((ca ^ asw[mt]) << 4);
                ldsm4(ah[mt], ad + OFF_AH);
                ldsm4(al[mt], ad + OFF_AL);
            }
#pragma unroll
            for (int jj = 0; jj < 4; ++jj) {      // 16 B-rows -> nt pair
                uint32_t cb = (uint32_t)(2 * s) + cBsel;
                uint32_t bd = stg + boff[jj] + ((cb ^ bsw[jj]) << 4);
                uint32_t rh[4], rl[4];
                ldsm4(rh, bd + OFF_BH);
                ldsm4(rl, bd + OFF_BL);
                const int n0 = 2 * jj, n1 = 2 * jj + 1;
                // three product sweeps; consecutive MMAs hit distinct accs
#pragma unroll
                for (int mt = 0; mt < 4; ++mt) {
                    mma16816(acc[mt][n0], ah[mt], rh);
                    mma16816(acc[mt][n1], ah[mt], rh + 2);
                }
#pragma unroll
                for (int mt = 0; mt < 4; ++mt) {
                    mma16816(acc[mt][n0], ah[mt], rl);
                    mma16816(acc[mt][n1], ah[mt], rl + 2);
                }
#pragma unroll
                for (int mt = 0; mt < 4; ++mt) {
                    mma16816(acc[mt][n0], al[mt], rh);
                    mma16816(acc[mt][n1], al[mt], rh + 2);
                }
            }
        }
    }

    // epilogue: + bias, f32x2 stores
    __syncthreads();
    const float* sbias = reinterpret_cast<const float*>(smem + SM_BIAS);
#pragma unroll
    for (int mt = 0; mt < 4; ++mt) {
#pragma unroll
        for (int nt = 0; nt < 8; ++nt) {
            int row = tm * BM + wm * 64 + mt * 16 + (lane >> 2);
            int cl = wn * 64 + nt * 8 + 2 * (lane & 3);
            float b0 = sbias[cl], b1 = sbias[cl + 1];
            float* p0 = out + (size_t)row * DIM + tn * BN + cl;
            float* p1 = p0 + 8 * DIM;
            *reinterpret_cast<float2*>(p0) =
                make_float2(acc[mt][nt][0] + b0, acc[mt][nt][1] + b1);
            *reinterpret_cast<float2*>(p1) =
                make_float2(acc[mt][nt][2] + b0, acc[mt][nt][3] + b1);
        }
    }
}

// ---------------------------------------------------------------------------
// Launch
// ---------------------------------------------------------------------------
extern "C" void kernel_launch(void* const* d_in, const int* in_sizes, int n_in,
                              void* d_out, int out_size) {
    const float* x = (const float*)d_in[0];
    const float* W = (const float*)d_in[1];
    const float* b = (const float*)d_in[2];
    float* out = (float*)d_out;

    split_kernel<<<16384, 256>>>(x, 0);
    split_kernel<<<16384, 256>>>(W, 1);

    cudaFuncSetAttribute(gemm_kernel, cudaFuncAttributeMaxDynamicSharedMemorySize,
                         SMEM_TOTAL);
    gemm_kernel<<<(DIM / BM) * (DIM / BN), THREADS, SMEM_TOTAL>>>(b, out);
}

// round 7
// speedup vs baseline: 2.2382x; 2.2382x over previous
#include <cuda_runtime.h>
#include <cuda_fp16.h>
#include <cstdint>

// ============================================================================
// out[4096,4096] = x @ W^T + b  (fp32).
// Single-pass fp16 warp-MMA GEMM (mma.sync m16n8k16.f32.f16.f16.f32).
// CTA tile 128x256x32, 8 warps @ 64x64, 4-stage cp.async pipeline.
// fp16 rounding error ~4e-4 (norm) < 1e-3 threshold.
// ============================================================================

#define DIM 4096
#define BM 128
#define BN 256
#define BK 32
#define NKT (DIM / BK)          // 128 k-tiles
#define THREADS 256
#define STAGES 4

// per-stage smem: A 8K | B 16K = 24KB (64B rows, XOR swizzle)
#define STAGE_BYTES 24576
#define OFF_A 0
#define OFF_B 8192
#define SM_BIAS 0               // 256 floats
#define SM_TILES 1024
#define SMEM_TOTAL (SM_TILES + STAGES * STAGE_BYTES)   // 99328

// ---------------------------------------------------------------------------
// Scratch: fp16 copies of x and W
// ---------------------------------------------------------------------------
__device__ __align__(256) __half g_x[(size_t)DIM * DIM];
__device__ __align__(256) __half g_w[(size_t)DIM * DIM];

// ---------------------------------------------------------------------------
// Helpers
// ---------------------------------------------------------------------------
static __device__ __forceinline__ uint32_t smem_u32(const void* p) {
    uint32_t a;
    asm("{ .reg .u64 t; cvta.to.shared.u64 t, %1; cvt.u32.u64 %0, t; }"
        : "=r"(a) : "l"(p));
    return a;
}

static __device__ __forceinline__ void cp16(uint32_t s, const void* g) {
    asm volatile("cp.async.cg.shared.global [%0], [%1], 16;" :: "r"(s), "l"(g));
}

static __device__ __forceinline__ void ldsm4(uint32_t* r, uint32_t a) {
    asm volatile("ldmatrix.sync.aligned.m8n8.x4.shared.b16 {%0,%1,%2,%3}, [%4];"
                 : "=r"(r[0]), "=r"(r[1]), "=r"(r[2]), "=r"(r[3]) : "r"(a));
}

static __device__ __forceinline__ void mma16816(float* c, const uint32_t* a,
                                                const uint32_t* b) {
    asm volatile(
        "mma.sync.aligned.m16n8k16.row.col.f32.f16.f16.f32 "
        "{%0,%1,%2,%3}, {%4,%5,%6,%7}, {%8,%9}, {%0,%1,%2,%3};"
        : "+f"(c[0]), "+f"(c[1]), "+f"(c[2]), "+f"(c[3])
        : "r"(a[0]), "r"(a[1]), "r"(a[2]), "r"(a[3]), "r"(b[0]), "r"(b[1]));
}

// ---------------------------------------------------------------------------
// Convert kernel: fp32 -> fp16 (8 elems/thread)
// ---------------------------------------------------------------------------
__global__ __launch_bounds__(256) void convert_kernel(const float* __restrict__ src,
                                                      int which) {
    __half* dst = which ? g_w : g_x;
    size_t i = ((size_t)blockIdx.x * blockDim.x + threadIdx.x) * 8;
    float4 v0 = *reinterpret_cast<const float4*>(src + i);
    float4 v1 = *reinterpret_cast<const float4*>(src + i + 4);
    __half2 h[4];
    h[0] = __floats2half2_rn(v0.x, v0.y);
    h[1] = __floats2half2_rn(v0.z, v0.w);
    h[2] = __floats2half2_rn(v1.x, v1.y);
    h[3] = __floats2half2_rn(v1.z, v1.w);
    *reinterpret_cast<uint4*>(dst + i) = *reinterpret_cast<const uint4*>(h);
}

// ---------------------------------------------------------------------------
// Stage loader: rows 64B wide; chunk c of row r stored at
//   r*64 + ((c ^ ((r>>1)&3))<<4)  -> conflict-free cp.async AND ldmatrix.
// A: 512 chunks, B: 1024 chunks -> 6 cp16/thread.
// ---------------------------------------------------------------------------
static __device__ __forceinline__ void load_stage(uint32_t sb, int stage, int kt,
                                                  int tm, int tn, int tid) {
    uint32_t st = sb + SM_TILES + stage * STAGE_BYTES;
    const uint32_t k0 = (uint32_t)kt * BK;
#pragma unroll
    for (int i = 0; i < 2; ++i) {          // A: 512 chunks / 256 thr
        int c = i * 256 + tid;
        int r = c >> 2, cc = c & 3;
        uint32_t so = (uint32_t)r * 64 + (uint32_t)((cc ^ ((r >> 1) & 3)) << 4);
        cp16(st + OFF_A + so, g_x + (size_t)(tm * BM + r) * DIM + k0 + cc * 8);
    }
#pragma unroll
    for (int i = 0; i < 4; ++i) {          // B: 1024 chunks / 256 thr
        int c = i * 256 + tid;
        int r = c >> 2, cc = c & 3;
        uint32_t so = (uint32_t)r * 64 + (uint32_t)((cc ^ ((r >> 1) & 3)) << 4);
        cp16(st + OFF_B + so, g_w + (size_t)(tn * BN + r) * DIM + k0 + cc * 8);
    }
}

// ---------------------------------------------------------------------------
// GEMM: D(128x256) = A*B^T over K, + bias.
// 8 warps: wm = wid&1 (2 x 64 rows), wn = wid>>1 (4 x 64 cols).
// ---------------------------------------------------------------------------
__global__ __launch_bounds__(THREADS, 1) void gemm_kernel(const float* __restrict__ bias,
                                                          float* __restrict__ out) {
    extern __shared__ __align__(1024) char smem[];
    uint32_t sb = smem_u32(smem);
    const int tid = threadIdx.x;
    const int lane = tid & 31, wid = tid >> 5;
    const int wm = wid & 1, wn = wid >> 1;

    // panel raster: panels of (8 tm x 16 tn) = 128 CTAs; wave ~fits in L2
    const int pid = blockIdx.x;
    const int panel = pid >> 7;
    const int ip = pid & 127;
    const int tm = panel * 8 + (ip & 7);
    const int tn = ip >> 3;

    reinterpret_cast<float*>(smem + SM_BIAS)[tid] = bias[tn * BN + tid];

    // per-lane ldmatrix address components (row*64 base + row-swizzle key)
    uint32_t aoff[4], asw[4];
#pragma unroll
    for (int mt = 0; mt < 4; ++mt) {
        int r = wm * 64 + mt * 16 + (lane & 15);
        aoff[mt] = (uint32_t)r * 64;
        asw[mt] = (uint32_t)((r >> 1) & 3);
    }
    uint32_t boff[4], bsw[4];
#pragma unroll
    for (int jj = 0; jj < 4; ++jj) {
        int r = wn * 64 + jj * 16 + ((lane >> 4) & 1) * 8 + (lane & 7);
        boff[jj] = (uint32_t)r * 64;
        bsw[jj] = (uint32_t)((r >> 1) & 3);
    }
    const uint32_t cAsel = (uint32_t)(lane >> 4);        // A k-chunk select
    const uint32_t cBsel = (uint32_t)((lane >> 3) & 1);  // B k-chunk select

    float acc[4][8][4];
#pragma unroll
    for (int mt = 0; mt < 4; ++mt)
#pragma unroll
        for (int nt = 0; nt < 8; ++nt)
#pragma unroll
            for (int k = 0; k < 4; ++k) acc[mt][nt][k] = 0.f;

    // prologue: 3 stages in flight
#pragma unroll
    for (int s = 0; s < STAGES - 1; ++s) {
        load_stage(sb, s, s, tm, tn, tid);
        asm volatile("cp.async.commit_group;");
    }

    for (int t = 0; t < NKT; ++t) {
        asm volatile("cp.async.wait_group 2;");
        __syncthreads();

        if (t + STAGES - 1 < NKT)
            load_stage(sb, (t + STAGES - 1) & (STAGES - 1), t + STAGES - 1, tm, tn, tid);
        asm volatile("cp.async.commit_group;");   // empty group ok -> uniform counting

        const uint32_t stg = sb + SM_TILES + (uint32_t)(t & (STAGES - 1)) * STAGE_BYTES;
#pragma unroll
        for (int s = 0; s < 2; ++s) {             // two k16 steps per BK=32
            uint32_t a[4][4];
#pragma unroll
            for (int mt = 0; mt < 4; ++mt) {
                uint32_t ca = (uint32_t)(2 * s) + cAsel;
                ldsm4(a[mt], stg + OFF_A + aoff[mt] + ((ca ^ asw[mt]) << 4));
            }
#pragma unroll
            for (int jj = 0; jj < 4; ++jj) {      // 16 B-rows -> nt pair
                uint32_t cb = (uint32_t)(2 * s) + cBsel;
                uint32_t rb[4];
                ldsm4(rb, stg + OFF_B + boff[jj] + ((cb ^ bsw[jj]) << 4));
                const int n0 = 2 * jj, n1 = 2 * jj + 1;
#pragma unroll
                for (int mt = 0; mt < 4; ++mt) {
                    mma16816(acc[mt][n0], a[mt], rb);
                    mma16816(acc[mt][n1], a[mt], rb + 2);
                }
            }
        }
    }

    // epilogue: + bias, f32x2 stores
    __syncthreads();
    const float* sbias = reinterpret_cast<const float*>(smem + SM_BIAS);
#pragma unroll
    for (int mt = 0; mt < 4; ++mt) {
#pragma unroll
        for (int nt = 0; nt < 8; ++nt) {
            int row = tm * BM + wm * 64 + mt * 16 + (lane >> 2);
            int cl = wn * 64 + nt * 8 + 2 * (lane & 3);
            float b0 = sbias[cl], b1 = sbias[cl + 1];
            float* p0 = out + (size_t)row * DIM + tn * BN + cl;
            float* p1 = p0 + 8 * DIM;
            *reinterpret_cast<float2*>(p0) =
                make_float2(acc[mt][nt][0] + b0, acc[mt][nt][1] + b1);
            *reinterpret_cast<float2*>(p1) =
                make_float2(acc[mt][nt][2] + b0, acc[mt][nt][3] + b1);
        }
    }
}

// ---------------------------------------------------------------------------
// Launch
// ---------------------------------------------------------------------------
extern "C" void kernel_launch(void* const* d_in, const int* in_sizes, int n_in,
                              void* d_out, int out_size) {
    const float* x = (const float*)d_in[0];
    const float* W = (const float*)d_in[1];
    const float* b = (const float*)d_in[2];
    float* out = (float*)d_out;

    // 4096*4096 / (256 threads * 8 elems) = 8192 blocks
    convert_kernel<<<8192, 256>>>(x, 0);
    convert_kernel<<<8192, 256>>>(W, 1);

    cudaFuncSetAttribute(gemm_kernel, cudaFuncAttributeMaxDynamicSharedMemorySize,
                         SMEM_TOTAL);
    gemm_kernel<<<(DIM / BM) * (DIM / BN), THREADS, SMEM_TOTAL>>>(b, out);
}

// round 8
// speedup vs baseline: 2.5926x; 1.1584x over previous
#include <cuda_runtime.h>
#include <cuda_fp16.h>
#include <cstdint>

// ============================================================================
// out[4096,4096] = x @ W^T + b  (fp32).
// Single-pass fp16 warp-MMA GEMM (mma.sync m16n8k16.f32.f16.f16.f32).
// CTA tile 128x256x32, 16 warps @ 64x32, 4-stage cp.async pipeline.
// ============================================================================

#define DIM 4096
#define BM 128
#define BN 256
#define BK 32
#define NKT (DIM / BK)          // 128 k-tiles
#define THREADS 512
#define STAGES 4

// per-stage smem: A 8K | B 16K = 24KB (64B rows, XOR swizzle)
#define STAGE_BYTES 24576
#define OFF_A 0
#define OFF_B 8192
#define SM_BIAS 0               // 256 floats
#define SM_TILES 1024
#define SMEM_TOTAL (SM_TILES + STAGES * STAGE_BYTES)   // 99328

// ---------------------------------------------------------------------------
// Scratch: fp16 copies of x and W
// ---------------------------------------------------------------------------
__device__ __align__(256) __half g_x[(size_t)DIM * DIM];
__device__ __align__(256) __half g_w[(size_t)DIM * DIM];

// ---------------------------------------------------------------------------
// Helpers
// ---------------------------------------------------------------------------
static __device__ __forceinline__ uint32_t smem_u32(const void* p) {
    uint32_t a;
    asm("{ .reg .u64 t; cvta.to.shared.u64 t, %1; cvt.u32.u64 %0, t; }"
        : "=r"(a) : "l"(p));
    return a;
}

static __device__ __forceinline__ void cp16(uint32_t s, const void* g) {
    asm volatile("cp.async.cg.shared.global [%0], [%1], 16;" :: "r"(s), "l"(g));
}

static __device__ __forceinline__ void ldsm4(uint32_t* r, uint32_t a) {
    asm volatile("ldmatrix.sync.aligned.m8n8.x4.shared.b16 {%0,%1,%2,%3}, [%4];"
                 : "=r"(r[0]), "=r"(r[1]), "=r"(r[2]), "=r"(r[3]) : "r"(a));
}

static __device__ __forceinline__ void mma16816(float* c, const uint32_t* a,
                                                const uint32_t* b) {
    asm volatile(
        "mma.sync.aligned.m16n8k16.row.col.f32.f16.f16.f32 "
        "{%0,%1,%2,%3}, {%4,%5,%6,%7}, {%8,%9}, {%0,%1,%2,%3};"
        : "+f"(c[0]), "+f"(c[1]), "+f"(c[2]), "+f"(c[3])
        : "r"(a[0]), "r"(a[1]), "r"(a[2]), "r"(a[3]), "r"(b[0]), "r"(b[1]));
}

// ---------------------------------------------------------------------------
// Convert kernel: fp32 -> fp16 (8 elems/thread)
// ---------------------------------------------------------------------------
__global__ __launch_bounds__(256) void convert_kernel(const float* __restrict__ src,
                                                      int which) {
    __half* dst = which ? g_w : g_x;
    size_t i = ((size_t)blockIdx.x * blockDim.x + threadIdx.x) * 8;
    float4 v0 = *reinterpret_cast<const float4*>(src + i);
    float4 v1 = *reinterpret_cast<const float4*>(src + i + 4);
    __half2 h[4];
    h[0] = __floats2half2_rn(v0.x, v0.y);
    h[1] = __floats2half2_rn(v0.z, v0.w);
    h[2] = __floats2half2_rn(v1.x, v1.y);
    h[3] = __floats2half2_rn(v1.z, v1.w);
    *reinterpret_cast<uint4*>(dst + i) = *reinterpret_cast<const uint4*>(h);
}

// ---------------------------------------------------------------------------
// Stage loader (512 threads): rows 64B wide; chunk c of row r stored at
//   r*64 + ((c ^ ((r>>1)&3))<<4)  -> conflict-free cp.async AND ldmatrix.
// A: 512 chunks (1/thread), B: 1024 chunks (2/thread) -> 3 cp16/thread.
// ---------------------------------------------------------------------------
static __device__ __forceinline__ void load_stage(uint32_t sb, int stage, int kt,
                                                  int tm, int tn, int tid) {
    uint32_t st = sb + SM_TILES + stage * STAGE_BYTES;
    const uint32_t k0 = (uint32_t)kt * BK;
    {                                       // A: 512 chunks / 512 thr
        int r = tid >> 2, cc = tid & 3;
        uint32_t so = (uint32_t)r * 64 + (uint32_t)((cc ^ ((r >> 1) & 3)) << 4);
        cp16(st + OFF_A + so, g_x + (size_t)(tm * BM + r) * DIM + k0 + cc * 8);
    }
#pragma unroll
    for (int i = 0; i < 2; ++i) {           // B: 1024 chunks / 512 thr
        int c = i * 512 + tid;
        int r = c >> 2, cc = c & 3;
        uint32_t so = (uint32_t)r * 64 + (uint32_t)((cc ^ ((r >> 1) & 3)) << 4);
        cp16(st + OFF_B + so, g_w + (size_t)(tn * BN + r) * DIM + k0 + cc * 8);
    }
}

// ---------------------------------------------------------------------------
// GEMM: D(128x256) = A*B^T over K, + bias.
// 16 warps: wm = wid&1 (2 x 64 rows), wn = wid>>1 (8 x 32 cols).
// ---------------------------------------------------------------------------
__global__ __launch_bounds__(THREADS, 1) void gemm_kernel(const float* __restrict__ bias,
                                                          float* __restrict__ out) {
    extern __shared__ __align__(1024) char smem[];
    uint32_t sb = smem_u32(smem);
    const int tid = threadIdx.x;
    const int lane = tid & 31, wid = tid >> 5;
    const int wm = wid & 1, wn = wid >> 1;

    // panel raster: panels of (8 tm x 16 tn) = 128 CTAs; wave ~fits in L2
    const int pid = blockIdx.x;
    const int panel = pid >> 7;
    const int ip = pid & 127;
    const int tm = panel * 8 + (ip & 7);
    const int tn = ip >> 3;

    if (tid < BN)
        reinterpret_cast<float*>(smem + SM_BIAS)[tid] = bias[tn * BN + tid];

    // per-lane ldmatrix address components (row*64 base + row-swizzle key)
    uint32_t aoff[4], asw[4];
#pragma unroll
    for (int mt = 0; mt < 4; ++mt) {
        int r = wm * 64 + mt * 16 + (lane & 15);
        aoff[mt] = (uint32_t)r * 64;
        asw[mt] = (uint32_t)((r >> 1) & 3);
    }
    uint32_t boff[2], bsw[2];
#pragma unroll
    for (int jj = 0; jj < 2; ++jj) {
        int r = wn * 32 + jj * 16 + ((lane >> 4) & 1) * 8 + (lane & 7);
        boff[jj] = (uint32_t)r * 64;
        bsw[jj] = (uint32_t)((r >> 1) & 3);
    }
    const uint32_t cAsel = (uint32_t)(lane >> 4);        // A k-chunk select
    const uint32_t cBsel = (uint32_t)((lane >> 3) & 1);  // B k-chunk select

    float acc[4][4][4];
#pragma unroll
    for (int mt = 0; mt < 4; ++mt)
#pragma unroll
        for (int nt = 0; nt < 4; ++nt)
#pragma unroll
            for (int k = 0; k < 4; ++k) acc[mt][nt][k] = 0.f;

    // prologue: 3 stages in flight
#pragma unroll
    for (int s = 0; s < STAGES - 1; ++s) {
        load_stage(sb, s, s, tm, tn, tid);
        asm volatile("cp.async.commit_group;");
    }

    for (int t = 0; t < NKT; ++t) {
        asm volatile("cp.async.wait_group 2;");
        __syncthreads();

        if (t + STAGES - 1 < NKT)
            load_stage(sb, (t + STAGES - 1) & (STAGES - 1), t + STAGES - 1, tm, tn, tid);
        asm volatile("cp.async.commit_group;");   // empty group ok -> uniform counting

        const uint32_t stg = sb + SM_TILES + (uint32_t)(t & (STAGES - 1)) * STAGE_BYTES;
#pragma unroll
        for (int s = 0; s < 2; ++s) {             // two k16 steps per BK=32
            uint32_t a[4][4];
#pragma unroll
            for (int mt = 0; mt < 4; ++mt) {
                uint32_t ca = (uint32_t)(2 * s) + cAsel;
                ldsm4(a[mt], stg + OFF_A + aoff[mt] + ((ca ^ asw[mt]) << 4));
            }
#pragma unroll
            for (int jj = 0; jj < 2; ++jj) {      // 16 B-rows -> nt pair
                uint32_t cb = (uint32_t)(2 * s) + cBsel;
                uint32_t rb[4];
                ldsm4(rb, stg + OFF_B + boff[jj] + ((cb ^ bsw[jj]) << 4));
                const int n0 = 2 * jj, n1 = 2 * jj + 1;
#pragma unroll
                for (int mt = 0; mt < 4; ++mt) {
                    mma16816(acc[mt][n0], a[mt], rb);
                    mma16816(acc[mt][n1], a[mt], rb + 2);
                }
            }
        }
    }

    // epilogue: + bias, f32x2 stores
    __syncthreads();
    const float* sbias = reinterpret_cast<const float*>(smem + SM_BIAS);
#pragma unroll
    for (int mt = 0; mt < 4; ++mt) {
#pragma unroll
        for (int nt = 0; nt < 4; ++nt) {
            int row = tm * BM + wm * 64 + mt * 16 + (lane >> 2);
            int cl = wn * 32 + nt * 8 + 2 * (lane & 3);
            float b0 = sbias[cl], b1 = sbias[cl + 1];
            float* p0 = out + (size_t)row * DIM + tn * BN + cl;
            float* p1 = p0 + 8 * DIM;
            *reinterpret_cast<float2*>(p0) =
                make_float2(acc[mt][nt][0] + b0, acc[mt][nt][1] + b1);
            *reinterpret_cast<float2*>(p1) =
                make_float2(acc[mt][nt][2] + b0, acc[mt][nt][3] + b1);
        }
    }
}

// ---------------------------------------------------------------------------
// Launch
// ---------------------------------------------------------------------------
extern "C" void kernel_launch(void* const* d_in, const int* in_sizes, int n_in,
                              void* d_out, int out_size) {
    const float* x = (const float*)d_in[0];
    const float* W = (const float*)d_in[1];
    const float* b = (const float*)d_in[2];
    float* out = (float*)d_out;

    // 4096*4096 / (256 threads * 8 elems) = 8192 blocks
    convert_kernel<<<8192, 256>>>(x, 0);
    convert_kernel<<<8192, 256>>>(W, 1);

    cudaFuncSetAttribute(gemm_kernel, cudaFuncAttributeMaxDynamicSharedMemorySize,
                         SMEM_TOTAL);
    gemm_kernel<<<(DIM / BM) * (DIM / BN), THREADS, SMEM_TOTAL>>>(b, out);
}

// round 11
// speedup vs baseline: 3.2052x; 1.2363x over previous
#include <cuda_runtime.h>
#include <cuda_fp16.h>
#include <cstdint>

// ============================================================================
// out[4096,4096] = x @ W^T + b  (fp32).
// Single-pass fp16 warp-MMA GEMM (mma.sync m16n8k16.f32.f16.f16.f32).
// CTA tile 128x128x64, 8 warps @ 64x32, 3-stage cp.async ring, 2 CTAs/SM.
// ============================================================================

#define DIM 4096
#define BM 128
#define BN 128
#define BK 64
#define NKT (DIM / BK)          // 64 k-tiles
#define THREADS 256
#define STAGES 3

// per-stage smem: A 16K | B 16K = 32KB (128B rows, 8x16B chunks, XOR swizzle)
#define STAGE_BYTES 32768
#define OFF_A 0
#define OFF_B 16384
#define SM_BIAS 0               // 128 floats
#define SM_TILES 1024
#define SMEM_TOTAL (SM_TILES + STAGES * STAGE_BYTES)   // 99328 (x2 CTAs = 194KB/SM)

// ---------------------------------------------------------------------------
// Scratch: fp16 copies of x and W
// ---------------------------------------------------------------------------
__device__ __align__(256) __half g_x[(size_t)DIM * DIM];
__device__ __align__(256) __half g_w[(size_t)DIM * DIM];

// ---------------------------------------------------------------------------
// Helpers
// ---------------------------------------------------------------------------
static __device__ __forceinline__ uint32_t smem_u32(const void* p) {
    uint32_t a;
    asm("{ .reg .u64 t; cvta.to.shared.u64 t, %1; cvt.u32.u64 %0, t; }"
        : "=r"(a) : "l"(p));
    return a;
}

static __device__ __forceinline__ void cp16(uint32_t s, const void* g) {
    asm volatile("cp.async.cg.shared.global [%0], [%1], 16;" :: "r"(s), "l"(g));
}

static __device__ __forceinline__ void ldsm4(uint32_t* r, uint32_t a) {
    asm volatile("ldmatrix.sync.aligned.m8n8.x4.shared.b16 {%0,%1,%2,%3}, [%4];"
                 : "=r"(r[0]), "=r"(r[1]), "=r"(r[2]), "=r"(r[3]) : "r"(a));
}

static __device__ __forceinline__ void mma16816(float* c, const uint32_t* a,
                                                const uint32_t* b) {
    asm volatile(
        "mma.sync.aligned.m16n8k16.row.col.f32.f16.f16.f32 "
        "{%0,%1,%2,%3}, {%4,%5,%6,%7}, {%8,%9}, {%0,%1,%2,%3};"
        : "+f"(c[0]), "+f"(c[1]), "+f"(c[2]), "+f"(c[3])
        : "r"(a[0]), "r"(a[1]), "r"(a[2]), "r"(a[3]), "r"(b[0]), "r"(b[1]));
}

// ---------------------------------------------------------------------------
// Convert kernel: fp32 -> fp16 (8 elems/thread)
// ---------------------------------------------------------------------------
__global__ __launch_bounds__(256) void convert_kernel(const float* __restrict__ src,
                                                      int which) {
    __half* dst = which ? g_w : g_x;
    size_t i = ((size_t)blockIdx.x * blockDim.x + threadIdx.x) * 8;
    float4 v0 = *reinterpret_cast<const float4*>(src + i);
    float4 v1 = *reinterpret_cast<const float4*>(src + i + 4);
    __half2 h[4];
    h[0] = __floats2half2_rn(v0.x, v0.y);
    h[1] = __floats2half2_rn(v0.z, v0.w);
    h[2] = __floats2half2_rn(v1.x, v1.y);
    h[3] = __floats2half2_rn(v1.z, v1.w);
    *reinterpret_cast<uint4*>(dst + i) = *reinterpret_cast<const uint4*>(h);
}

// ---------------------------------------------------------------------------
// Stage loader (256 threads): rows 128B wide (64 halfs); chunk cc of row r at
//   r*128 + ((cc ^ (r&7))<<4)  -> conflict-free for cp.async AND ldmatrix.
// A: 1024 chunks (4/thr), B: 1024 chunks (4/thr) -> 8 cp16/thread.
// ---------------------------------------------------------------------------
static __device__ __forceinline__ void load_stage(uint32_t sb, int stage, int kt,
                                                  int tm, int tn, int tid) {
    uint32_t st = sb + SM_TILES + stage * STAGE_BYTES;
    const uint32_t k0 = (uint32_t)kt * BK;
#pragma unroll
    for (int i = 0; i < 4; ++i) {          // A: 1024 chunks / 256 thr
        int c = i * 256 + tid;
        int r = c >> 3, cc = c & 7;
        uint32_t so = (uint32_t)r * 128 + (uint32_t)((cc ^ (r & 7)) << 4);
        cp16(st + OFF_A + so, g_x + (size_t)(tm * BM + r) * DIM + k0 + cc * 8);
    }
#pragma unroll
    for (int i = 0; i < 4; ++i) {          // B: 1024 chunks / 256 thr
        int c = i * 256 + tid;
        int r = c >> 3, cc = c & 7;
        uint32_t so = (uint32_t)r * 128 + (uint32_t)((cc ^ (r & 7)) << 4);
        cp16(st + OFF_B + so, g_w + (size_t)(tn * BN + r) * DIM + k0 + cc * 8);
    }
}

// ---------------------------------------------------------------------------
// GEMM: D(128x128) = A*B^T over K, + bias.
// 8 warps: wm = wid&1 (2 x 64 rows), wn = wid>>1 (4 x 32 cols).
// ---------------------------------------------------------------------------
__global__ __launch_bounds__(THREADS, 2) void gemm_kernel(const float* __restrict__ bias,
                                                          float* __restrict__ out) {
    extern __shared__ __align__(1024) char smem[];
    uint32_t sb = smem_u32(smem);
    const int tid = threadIdx.x;
    const int lane = tid & 31, wid = tid >> 5;
    const int wm = wid & 1, wn = wid >> 1;

    // raster: tm fast within full column sweep -> A panel L2-resident per wave
    const int pid = blockIdx.x;
    const int tm = pid & 31;               // 0..31
    const int tn = pid >> 5;               // 0..31

    if (tid < BN)
        reinterpret_cast<float*>(smem + SM_BIAS)[tid] = bias[tn * BN + tid];

    // per-lane ldmatrix address components (row*128 base + row-swizzle key r&7)
    uint32_t aoff[4], asw[4];
#pragma unroll
    for (int mt = 0; mt < 4; ++mt) {
        int r = wm * 64 + mt * 16 + (lane & 15);
        aoff[mt] = (uint32_t)r * 128;
        asw[mt] = (uint32_t)(r & 7);
    }
    uint32_t boff[2], bsw[2];
#pragma unroll
    for (int jj = 0; jj < 2; ++jj) {
        int r = wn * 32 + jj * 16 + ((lane >> 4) & 1) * 8 + (lane & 7);
        boff[jj] = (uint32_t)r * 128;
        bsw[jj] = (uint32_t)(r & 7);
    }
    const uint32_t cAsel = (uint32_t)(lane >> 4);        // A k-chunk select (0/1)
    const uint32_t cBsel = (uint32_t)((lane >> 3) & 1);  // B k-chunk select (0/1)

    float acc[4][4][4];
#pragma unroll
    for (int mt = 0; mt < 4; ++mt)
#pragma unroll
        for (int nt = 0; nt < 4; ++nt)
#pragma unroll
            for (int k = 0; k < 4; ++k) acc[mt][nt][k] = 0.f;

    // prologue: 2 stages in flight
    load_stage(sb, 0, 0, tm, tn, tid);
    asm volatile("cp.async.commit_group;");
    load_stage(sb, 1, 1, tm, tn, tid);
    asm volatile("cp.async.commit_group;");

    int scur = 0;                           // ring index t % 3
    for (int t = 0; t < NKT; ++t) {
        asm volatile("cp.async.wait_group 1;");
        __syncthreads();

        if (t + 2 < NKT) {
            int sld = scur + 2; if (sld >= STAGES) sld -= STAGES;
            load_stage(sb, sld, t + 2, tm, tn, tid);
        }
        asm volatile("cp.async.commit_group;");   // empty group ok

        const uint32_t stg = sb + SM_TILES + (uint32_t)scur * STAGE_BYTES;
#pragma unroll
        for (int s = 0; s < 4; ++s) {             // four k16 steps per BK=64
            uint32_t a[4][4];
#pragma unroll
            for (int mt = 0; mt < 4; ++mt) {
                uint32_t ca = (uint32_t)(2 * s) + cAsel;
                ldsm4(a[mt], stg + OFF_A + aoff[mt] + ((ca ^ asw[mt]) << 4));
            }
#pragma unroll
            for (int jj = 0; jj < 2; ++jj) {      // 16 B-rows -> nt pair
                uint32_t cb = (uint32_t)(2 * s) + cBsel;
                uint32_t rb[4];
                ldsm4(rb, stg + OFF_B + boff[jj] + ((cb ^ bsw[jj]) << 4));
                const int n0 = 2 * jj, n1 = 2 * jj + 1;
#pragma unroll
                for (int mt = 0; mt < 4; ++mt) {
                    mma16816(acc[mt][n0], a[mt], rb);
                    mma16816(acc[mt][n1], a[mt], rb + 2);
                }
            }
        }
        scur = (scur == STAGES - 1) ? 0 : scur + 1;
    }

    // epilogue: + bias, f32x2 stores
    __syncthreads();
    const float* sbias = reinterpret_cast<const float*>(smem + SM_BIAS);
#pragma unroll
    for (int mt = 0; mt < 4; ++mt) {
#pragma unroll
        for (int nt = 0; nt < 4; ++nt) {
            int row = tm * BM + wm * 64 + mt * 16 + (lane >> 2);
            int cl = wn * 32 + nt * 8 + 2 * (lane & 3);
            float b0 = sbias[cl], b1 = sbias[cl + 1];
            float* p0 = out + (size_t)row * DIM + tn * BN + cl;
            float* p1 = p0 + 8 * DIM;
            *reinterpret_cast<float2*>(p0) =
                make_float2(acc[mt][nt][0] + b0, acc[mt][nt][1] + b1);
            *reinterpret_cast<float2*>(p1) =
                make_float2(acc[mt][nt][2] + b0, acc[mt][nt][3] + b1);
        }
    }
}

// ---------------------------------------------------------------------------
// Launch
// ---------------------------------------------------------------------------
extern "C" void kernel_launch(void* const* d_in, const int* in_sizes, int n_in,
                              void* d_out, int out_size) {
    const float* x = (const float*)d_in[0];
    const float* W = (const float*)d_in[1];
    const float* b = (const float*)d_in[2];
    float* out = (float*)d_out;

    // 4096*4096 / (256 threads * 8 elems) = 8192 blocks
    convert_kernel<<<8192, 256>>>(x, 0);
    convert_kernel<<<8192, 256>>>(W, 1);

    cudaFuncSetAttribute(gemm_kernel, cudaFuncAttributeMaxDynamicSharedMemorySize,
                         SMEM_TOTAL);
    gemm_kernel<<<(DIM / BM) * (DIM / BN), THREADS, SMEM_TOTAL>>>(b, out);
}

// round 12
// speedup vs baseline: 3.2452x; 1.0125x over previous
#include <cuda_runtime.h>
#include <cuda_fp16.h>
#include <cstdint>

// ============================================================================
// out[4096,4096] = x @ W^T + b  (fp32).
// Single-pass fp16 warp-MMA GEMM (mma.sync m16n8k16.f32.f16.f16.f32).
// CTA tile 128x128x64, 4 warps @ 64x64, 3-stage cp.async ring, 2 CTAs/SM.
// ============================================================================

#define DIM 4096
#define BM 128
#define BN 128
#define BK 64
#define NKT (DIM / BK)          // 64 k-tiles
#define THREADS 128
#define STAGES 3

// per-stage smem: A 16K | B 16K = 32KB (128B rows, 8x16B chunks, XOR swizzle)
#define STAGE_BYTES 32768
#define OFF_A 0
#define OFF_B 16384
#define SM_BIAS 0               // 128 floats
#define SM_TILES 1024
#define SMEM_TOTAL (SM_TILES + STAGES * STAGE_BYTES)   // 99328 (x2 CTAs = 194KB/SM)

// ---------------------------------------------------------------------------
// Scratch: fp16 copies of x and W
// ---------------------------------------------------------------------------
__device__ __align__(256) __half g_x[(size_t)DIM * DIM];
__device__ __align__(256) __half g_w[(size_t)DIM * DIM];

// ---------------------------------------------------------------------------
// Helpers
// ---------------------------------------------------------------------------
static __device__ __forceinline__ uint32_t smem_u32(const void* p) {
    uint32_t a;
    asm("{ .reg .u64 t; cvta.to.shared.u64 t, %1; cvt.u32.u64 %0, t; }"
        : "=r"(a) : "l"(p));
    return a;
}

static __device__ __forceinline__ void cp16(uint32_t s, const void* g) {
    asm volatile("cp.async.cg.shared.global [%0], [%1], 16;" :: "r"(s), "l"(g));
}

static __device__ __forceinline__ void ldsm4(uint32_t* r, uint32_t a) {
    asm volatile("ldmatrix.sync.aligned.m8n8.x4.shared.b16 {%0,%1,%2,%3}, [%4];"
                 : "=r"(r[0]), "=r"(r[1]), "=r"(r[2]), "=r"(r[3]) : "r"(a));
}

static __device__ __forceinline__ void mma16816(float* c, const uint32_t* a,
                                                const uint32_t* b) {
    asm volatile(
        "mma.sync.aligned.m16n8k16.row.col.f32.f16.f16.f32 "
        "{%0,%1,%2,%3}, {%4,%5,%6,%7}, {%8,%9}, {%0,%1,%2,%3};"
        : "+f"(c[0]), "+f"(c[1]), "+f"(c[2]), "+f"(c[3])
        : "r"(a[0]), "r"(a[1]), "r"(a[2]), "r"(a[3]), "r"(b[0]), "r"(b[1]));
}

// ---------------------------------------------------------------------------
// Convert kernel: fp32 -> fp16 (8 elems/thread); one launch handles x AND W.
// ---------------------------------------------------------------------------
__global__ __launch_bounds__(256) void convert_kernel(const float* __restrict__ x,
                                                      const float* __restrict__ W) {
    const int half_grid = (int)(gridDim.x >> 1);
    const float* src = (blockIdx.x < half_grid) ? x : W;
    __half* dst = (blockIdx.x < half_grid) ? g_x : g_w;
    int blk = (blockIdx.x < half_grid) ? blockIdx.x : (blockIdx.x - half_grid);
    size_t i = ((size_t)blk * blockDim.x + threadIdx.x) * 8;
    float4 v0 = *reinterpret_cast<const float4*>(src + i);
    float4 v1 = *reinterpret_cast<const float4*>(src + i + 4);
    __half2 h[4];
    h[0] = __floats2half2_rn(v0.x, v0.y);
    h[1] = __floats2half2_rn(v0.z, v0.w);
    h[2] = __floats2half2_rn(v1.x, v1.y);
    h[3] = __floats2half2_rn(v1.z, v1.w);
    *reinterpret_cast<uint4*>(dst + i) = *reinterpret_cast<const uint4*>(h);
}

// ---------------------------------------------------------------------------
// Stage loader (128 threads): rows 128B wide (64 halfs); chunk cc of row r at
//   r*128 + ((cc ^ (r&7))<<4)  -> conflict-free for cp.async AND ldmatrix.
// A: 1024 chunks (8/thr), B: 1024 chunks (8/thr) -> 16 cp16/thread.
// ---------------------------------------------------------------------------
static __device__ __forceinline__ void load_stage(uint32_t sb, int stage, int kt,
                                                  int tm, int tn, int tid) {
    uint32_t st = sb + SM_TILES + stage * STAGE_BYTES;
    const uint32_t k0 = (uint32_t)kt * BK;
#pragma unroll
    for (int i = 0; i < 8; ++i) {          // A: 1024 chunks / 128 thr
        int c = i * 128 + tid;
        int r = c >> 3, cc = c & 7;
        uint32_t so = (uint32_t)r * 128 + (uint32_t)((cc ^ (r & 7)) << 4);
        cp16(st + OFF_A + so, g_x + (size_t)(tm * BM + r) * DIM + k0 + cc * 8);
    }
#pragma unroll
    for (int i = 0; i < 8; ++i) {          // B: 1024 chunks / 128 thr
        int c = i * 128 + tid;
        int r = c >> 3, cc = c & 7;
        uint32_t so = (uint32_t)r * 128 + (uint32_t)((cc ^ (r & 7)) << 4);
        cp16(st + OFF_B + so, g_w + (size_t)(tn * BN + r) * DIM + k0 + cc * 8);
    }
}

// ---------------------------------------------------------------------------
// GEMM: D(128x128) = A*B^T over K, + bias.
// 4 warps @ 64x64: wm = wid&1 (2 x 64 rows), wn = wid>>1 (2 x 64 cols).
// ---------------------------------------------------------------------------
__global__ __launch_bounds__(THREADS, 2) void gemm_kernel(const float* __restrict__ bias,
                                                          float* __restrict__ out) {
    extern __shared__ __align__(1024) char smem[];
    uint32_t sb = smem_u32(smem);
    const int tid = threadIdx.x;
    const int lane = tid & 31, wid = tid >> 5;
    const int wm = wid & 1, wn = wid >> 1;

    // raster: tm fast within full column sweep -> A panel L2-resident per wave
    const int pid = blockIdx.x;
    const int tm = pid & 31;               // 0..31
    const int tn = pid >> 5;               // 0..31

    reinterpret_cast<float*>(smem + SM_BIAS)[tid] = bias[tn * BN + tid];

    // per-lane ldmatrix address components (row*128 base + row-swizzle key r&7)
    uint32_t aoff[4], asw[4];
#pragma unroll
    for (int mt = 0; mt < 4; ++mt) {
        int r = wm * 64 + mt * 16 + (lane & 15);
        aoff[mt] = (uint32_t)r * 128;
        asw[mt] = (uint32_t)(r & 7);
    }
    uint32_t boff[4], bsw[4];
#pragma unroll
    for (int jj = 0; jj < 4; ++jj) {
        int r = wn * 64 + jj * 16 + ((lane >> 4) & 1) * 8 + (lane & 7);
        boff[jj] = (uint32_t)r * 128;
        bsw[jj] = (uint32_t)(r & 7);
    }
    const uint32_t cAsel = (uint32_t)(lane >> 4);        // A k-chunk select (0/1)
    const uint32_t cBsel = (uint32_t)((lane >> 3) & 1);  // B k-chunk select (0/1)

    float acc[4][8][4];
#pragma unroll
    for (int mt = 0; mt < 4; ++mt)
#pragma unroll
        for (int nt = 0; nt < 8; ++nt)
#pragma unroll
            for (int k = 0; k < 4; ++k) acc[mt][nt][k] = 0.f;

    // prologue: 2 stages in flight
    load_stage(sb, 0, 0, tm, tn, tid);
    asm volatile("cp.async.commit_group;");
    load_stage(sb, 1, 1, tm, tn, tid);
    asm volatile("cp.async.commit_group;");

    int scur = 0;                           // ring index t % 3
    for (int t = 0; t < NKT; ++t) {
        asm volatile("cp.async.wait_group 1;");
        __syncthreads();

        if (t + 2 < NKT) {
            int sld = scur + 2; if (sld >= STAGES) sld -= STAGES;
            load_stage(sb, sld, t + 2, tm, tn, tid);
        }
        asm volatile("cp.async.commit_group;");   // empty group ok

        const uint32_t stg = sb + SM_TILES + (uint32_t)scur * STAGE_BYTES;
#pragma unroll
        for (int s = 0; s < 4; ++s) {             // four k16 steps per BK=64
            uint32_t a[4][4];
#pragma unroll
            for (int mt = 0; mt < 4; ++mt) {
                uint32_t ca = (uint32_t)(2 * s) + cAsel;
                ldsm4(a[mt], stg + OFF_A + aoff[mt] + ((ca ^ asw[mt]) << 4));
            }
#pragma unroll
            for (int jj = 0; jj < 4; ++jj) {      // 16 B-rows -> nt pair
                uint32_t cb = (uint32_t)(2 * s) + cBsel;
                uint32_t rb[4];
                ldsm4(rb, stg + OFF_B + boff[jj] + ((cb ^ bsw[jj]) << 4));
                const int n0 = 2 * jj, n1 = 2 * jj + 1;
#pragma unroll
                for (int mt = 0; mt < 4; ++mt) {
                    mma16816(acc[mt][n0], a[mt], rb);
                    mma16816(acc[mt][n1], a[mt], rb + 2);
                }
            }
        }
        scur = (scur == STAGES - 1) ? 0 : scur + 1;
    }

    // epilogue: + bias, f32x2 stores
    __syncthreads();
    const float* sbias = reinterpret_cast<const float*>(smem + SM_BIAS);
#pragma unroll
    for (int mt = 0; mt < 4; ++mt) {
#pragma unroll
        for (int nt = 0; nt < 8; ++nt) {
            int row = tm * BM + wm * 64 + mt * 16 + (lane >> 2);
            int cl = wn * 64 + nt * 8 + 2 * (lane & 3);
            float b0 = sbias[cl], b1 = sbias[cl + 1];
            float* p0 = out + (size_t)row * DIM + tn * BN + cl;
            float* p1 = p0 + 8 * DIM;
            *reinterpret_cast<float2*>(p0) =
                make_float2(acc[mt][nt][0] + b0, acc[mt][nt][1] + b1);
            *reinterpret_cast<float2*>(p1) =
                make_float2(acc[mt][nt][2] + b0, acc[mt][nt][3] + b1);
        }
    }
}

// ---------------------------------------------------------------------------
// Launch
// ---------------------------------------------------------------------------
extern "C" void kernel_launch(void* const* d_in, const int* in_sizes, int n_in,
                              void* d_out, int out_size) {
    const float* x = (const float*)d_in[0];
    const float* W = (const float*)d_in[1];
    const float* b = (const float*)d_in[2];
    float* out = (float*)d_out;

    // 2 * (4096*4096 / (256 threads * 8 elems)) = 16384 blocks, one launch
    convert_kernel<<<16384, 256>>>(x, W);

    cudaFuncSetAttribute(gemm_kernel, cudaFuncAttributeMaxDynamicSharedMemorySize,
                         SMEM_TOTAL);
    gemm_kernel<<<(DIM / BM) * (DIM / BN), THREADS, SMEM_TOTAL>>>(b, out);
}

// round 13
// speedup vs baseline: 3.5213x; 1.0851x over previous
#include <cuda_runtime.h>
#include <cuda_fp16.h>
#include <cstdint>

// ============================================================================
// out[4096,4096] = x @ W^T + b  (fp32).
// Single-pass fp16 warp-MMA GEMM (mma.sync m16n8k16.f32.f16.f16.f32).
// CTA tile 128x128x64, 4 warps @ 64x64, 3-stage cp.async ring, 2 CTAs/SM.
// All fragments hoisted per k-step; k-loop unrolled by ring period (3).
// ============================================================================

#define DIM 4096
#define BM 128
#define BN 128
#define BK 64
#define NKT (DIM / BK)          // 64 k-tiles
#define THREADS 128
#define STAGES 3

// per-stage smem: A 16K | B 16K = 32KB (128B rows, 8x16B chunks, XOR swizzle)
#define STAGE_BYTES 32768
#define OFF_A 0
#define OFF_B 16384
#define SM_BIAS 0               // 128 floats
#define SM_TILES 1024
#define SMEM_TOTAL (SM_TILES + STAGES * STAGE_BYTES)   // 99328 (x2 CTAs = 194KB/SM)

// ---------------------------------------------------------------------------
// Scratch: fp16 copies of x and W
// ---------------------------------------------------------------------------
__device__ __align__(256) __half g_x[(size_t)DIM * DIM];
__device__ __align__(256) __half g_w[(size_t)DIM * DIM];

// ---------------------------------------------------------------------------
// Helpers
// ---------------------------------------------------------------------------
static __device__ __forceinline__ uint32_t smem_u32(const void* p) {
    uint32_t a;
    asm("{ .reg .u64 t; cvta.to.shared.u64 t, %1; cvt.u32.u64 %0, t; }"
        : "=r"(a) : "l"(p));
    return a;
}

static __device__ __forceinline__ void cp16(uint32_t s, const void* g) {
    asm volatile("cp.async.cg.shared.global [%0], [%1], 16;" :: "r"(s), "l"(g));
}

static __device__ __forceinline__ void ldsm4(uint32_t* r, uint32_t a) {
    asm volatile("ldmatrix.sync.aligned.m8n8.x4.shared.b16 {%0,%1,%2,%3}, [%4];"
                 : "=r"(r[0]), "=r"(r[1]), "=r"(r[2]), "=r"(r[3]) : "r"(a));
}

static __device__ __forceinline__ void mma16816(float* c, const uint32_t* a,
                                                const uint32_t* b) {
    asm volatile(
        "mma.sync.aligned.m16n8k16.row.col.f32.f16.f16.f32 "
        "{%0,%1,%2,%3}, {%4,%5,%6,%7}, {%8,%9}, {%0,%1,%2,%3};"
        : "+f"(c[0]), "+f"(c[1]), "+f"(c[2]), "+f"(c[3])
        : "r"(a[0]), "r"(a[1]), "r"(a[2]), "r"(a[3]), "r"(b[0]), "r"(b[1]));
}

// ---------------------------------------------------------------------------
// Convert kernel: fp32 -> fp16 (8 elems/thread); one launch handles x AND W.
// ---------------------------------------------------------------------------
__global__ __launch_bounds__(256) void convert_kernel(const float* __restrict__ x,
                                                      const float* __restrict__ W) {
    const int half_grid = (int)(gridDim.x >> 1);
    const float* src = (blockIdx.x < half_grid) ? x : W;
    __half* dst = (blockIdx.x < half_grid) ? g_x : g_w;
    int blk = (blockIdx.x < half_grid) ? blockIdx.x : (blockIdx.x - half_grid);
    size_t i = ((size_t)blk * blockDim.x + threadIdx.x) * 8;
    float4 v0 = *reinterpret_cast<const float4*>(src + i);
    float4 v1 = *reinterpret_cast<const float4*>(src + i + 4);
    __half2 h[4];
    h[0] = __floats2half2_rn(v0.x, v0.y);
    h[1] = __floats2half2_rn(v0.z, v0.w);
    h[2] = __floats2half2_rn(v1.x, v1.y);
    h[3] = __floats2half2_rn(v1.z, v1.w);
    *reinterpret_cast<uint4*>(dst + i) = *reinterpret_cast<const uint4*>(h);
}

// ---------------------------------------------------------------------------
// Stage loader (128 threads): rows 128B wide (64 halfs); chunk cc of row r at
//   r*128 + ((cc ^ (r&7))<<4)  -> conflict-free for cp.async AND ldmatrix.
// A: 1024 chunks (8/thr), B: 1024 chunks (8/thr) -> 16 cp16/thread.
// ---------------------------------------------------------------------------
static __device__ __forceinline__ void load_stage(uint32_t sb, int stage, int kt,
                                                  int tm, int tn, int tid) {
    uint32_t st = sb + SM_TILES + stage * STAGE_BYTES;
    const uint32_t k0 = (uint32_t)kt * BK;
#pragma unroll
    for (int i = 0; i < 8; ++i) {          // A: 1024 chunks / 128 thr
        int c = i * 128 + tid;
        int r = c >> 3, cc = c & 7;
        uint32_t so = (uint32_t)r * 128 + (uint32_t)((cc ^ (r & 7)) << 4);
        cp16(st + OFF_A + so, g_x + (size_t)(tm * BM + r) * DIM + k0 + cc * 8);
    }
#pragma unroll
    for (int i = 0; i < 8; ++i) {          // B: 1024 chunks / 128 thr
        int c = i * 128 + tid;
        int r = c >> 3, cc = c & 7;
        uint32_t so = (uint32_t)r * 128 + (uint32_t)((cc ^ (r & 7)) << 4);
        cp16(st + OFF_B + so, g_w + (size_t)(tn * BN + r) * DIM + k0 + cc * 8);
    }
}

// ---------------------------------------------------------------------------
// GEMM: D(128x128) = A*B^T over K, + bias.
// 4 warps @ 64x64: wm = wid&1 (2 x 64 rows), wn = wid>>1 (2 x 64 cols).
// ---------------------------------------------------------------------------
__global__ __launch_bounds__(THREADS, 2) void gemm_kernel(const float* __restrict__ bias,
                                                          float* __restrict__ out) {
    extern __shared__ __align__(1024) char smem[];
    uint32_t sb = smem_u32(smem);
    const int tid = threadIdx.x;
    const int lane = tid & 31, wid = tid >> 5;
    const int wm = wid & 1, wn = wid >> 1;

    // raster: tm fast within full column sweep -> A panel L2-resident per wave
    const int pid = blockIdx.x;
    const int tm = pid & 31;               // 0..31
    const int tn = pid >> 5;               // 0..31

    reinterpret_cast<float*>(smem + SM_BIAS)[tid] = bias[tn * BN + tid];

    // per-lane ldmatrix address components (row*128 base + row-swizzle key r&7)
    uint32_t aoff[4], asw[4];
#pragma unroll
    for (int mt = 0; mt < 4; ++mt) {
        int r = wm * 64 + mt * 16 + (lane & 15);
        aoff[mt] = (uint32_t)r * 128;
        asw[mt] = (uint32_t)(r & 7);
    }
    uint32_t boff[4], bsw[4];
#pragma unroll
    for (int jj = 0; jj < 4; ++jj) {
        int r = wn * 64 + jj * 16 + ((lane >> 4) & 1) * 8 + (lane & 7);
        boff[jj] = (uint32_t)r * 128;
        bsw[jj] = (uint32_t)(r & 7);
    }
    const uint32_t cAsel = (uint32_t)(lane >> 4);        // A k-chunk select (0/1)
    const uint32_t cBsel = (uint32_t)((lane >> 3) & 1);  // B k-chunk select (0/1)

    float acc[4][8][4];
#pragma unroll
    for (int mt = 0; mt < 4; ++mt)
#pragma unroll
        for (int nt = 0; nt < 8; ++nt)
#pragma unroll
            for (int k = 0; k < 4; ++k) acc[mt][nt][k] = 0.f;

    // prologue: 2 stages in flight
    load_stage(sb, 0, 0, tm, tn, tid);
    asm volatile("cp.async.commit_group;");
    load_stage(sb, 1, 1, tm, tn, tid);
    asm volatile("cp.async.commit_group;");

    // one k-tile body at compile-time stage index
    auto body = [&](int t, int sc) {
        asm volatile("cp.async.wait_group 1;");
        __syncthreads();

        if (t + 2 < NKT) {
            int sld = sc + 2; if (sld >= STAGES) sld -= STAGES;
            load_stage(sb, sld, t + 2, tm, tn, tid);
        }
        asm volatile("cp.async.commit_group;");   // empty group ok

        const uint32_t stg = sb + SM_TILES + (uint32_t)sc * STAGE_BYTES;
#pragma unroll
        for (int s = 0; s < 4; ++s) {             // four k16 steps per BK=64
            uint32_t a[4][4], b[4][4];
#pragma unroll
            for (int mt = 0; mt < 4; ++mt) {
                uint32_t ca = (uint32_t)(2 * s) + cAsel;
                ldsm4(a[mt], stg + OFF_A + aoff[mt] + ((ca ^ asw[mt]) << 4));
            }
#pragma unroll
            for (int jj = 0; jj < 4; ++jj) {
                uint32_t cb = (uint32_t)(2 * s) + cBsel;
                ldsm4(b[jj], stg + OFF_B + boff[jj] + ((cb ^ bsw[jj]) << 4));
            }
            // 32 MMAs, no loads interleaved; consecutive MMAs hit distinct accs
#pragma unroll
            for (int jj = 0; jj < 4; ++jj) {
                const int n0 = 2 * jj, n1 = 2 * jj + 1;
#pragma unroll
                for (int mt = 0; mt < 4; ++mt) {
                    mma16816(acc[mt][n0], a[mt], b[jj]);
                    mma16816(acc[mt][n1], a[mt], b[jj] + 2);
                }
            }
        }
    };

    // 64 k-tiles = 21 x (ring of 3, compile-time stages) + 1 tail (stage 0)
#pragma unroll 1
    for (int tt = 0; tt < NKT - 1; tt += 3) {
        body(tt, 0);
        body(tt + 1, 1);
        body(tt + 2, 2);
    }
    body(NKT - 1, 0);

    // epilogue: + bias, f32x2 stores
    __syncthreads();
    const float* sbias = reinterpret_cast<const float*>(smem + SM_BIAS);
#pragma unroll
    for (int mt = 0; mt < 4; ++mt) {
#pragma unroll
        for (int nt = 0; nt < 8; ++nt) {
            int row = tm * BM + wm * 64 + mt * 16 + (lane >> 2);
            int cl = wn * 64 + nt * 8 + 2 * (lane & 3);
            float b0 = sbias[cl], b1 = sbias[cl + 1];
            float* p0 = out + (size_t)row * DIM + tn * BN + cl;
            float* p1 = p0 + 8 * DIM;
            *reinterpret_cast<float2*>(p0) =
                make_float2(acc[mt][nt][0] + b0, acc[mt][nt][1] + b1);
            *reinterpret_cast<float2*>(p1) =
                make_float2(acc[mt][nt][2] + b0, acc[mt][nt][3] + b1);
        }
    }
}

// ---------------------------------------------------------------------------
// Launch
// ---------------------------------------------------------------------------
extern "C" void kernel_launch(void* const* d_in, const int* in_sizes, int n_in,
                              void* d_out, int out_size) {
    const float* x = (const float*)d_in[0];
    const float* W = (const float*)d_in[1];
    const float* b = (const float*)d_in[2];
    float* out = (float*)d_out;

    // 2 * (4096*4096 / (256 threads * 8 elems)) = 16384 blocks, one launch
    convert_kernel<<<16384, 256>>>(x, W);

    cudaFuncSetAttribute(gemm_kernel, cudaFuncAttributeMaxDynamicSharedMemorySize,
                         SMEM_TOTAL);
    gemm_kernel<<<(DIM / BM) * (DIM / BN), THREADS, SMEM_TOTAL>>>(b, out);
}